// round 1
// baseline (speedup 1.0000x reference)
#include <cuda_runtime.h>

#define NN   65536          // total nodes (G*N)
#define FIN  64
#define DD   128
#define RR   4
#define EE   1572864
#define GG   512
#define SEGS (NN*RR)        // 262144 (node,relation) segments
#define KCAT (RR*DD)        // 512

// ---- scratch (static device globals; no runtime allocation) ----
__device__ __align__(16) float g_hA[(size_t)NN*DD];       // 32 MB
__device__ __align__(16) float g_hB[(size_t)NN*DD];       // 32 MB
__device__ __align__(16) float g_mean[(size_t)SEGS*DD];   // 134 MB
__device__ int   g_cnt[SEGS];
__device__ float g_inv[SEGS];

// ---------------- small prep kernels ----------------
__global__ void k_zero_cnt() {
    int i = blockIdx.x*blockDim.x + threadIdx.x;
    if (i < SEGS) g_cnt[i] = 0;
}

__global__ void k_count(const int* __restrict__ ei, const int* __restrict__ ea) {
    int e = blockIdx.x*blockDim.x + threadIdx.x;
    if (e < EE) atomicAdd(&g_cnt[ei[EE + e]*RR + ea[e]], 1);
}

__global__ void k_inv() {
    int i = blockIdx.x*blockDim.x + threadIdx.x;
    if (i < SEGS) { int c = g_cnt[i]; g_inv[i] = 1.0f / (float)(c > 0 ? c : 1); }
}

// h = x @ W_emb + b_emb   (65536x64 @ 64x128, trivial FLOPs)
__global__ void k_embed(const float* __restrict__ x, const float* __restrict__ W,
                        const float* __restrict__ b) {
    int idx = blockIdx.x*blockDim.x + threadIdx.x;   // NN*DD threads exactly
    int n = idx >> 7, d = idx & 127;
    const float* xr = x + n*FIN;
    float acc = b[d];
    #pragma unroll 16
    for (int k = 0; k < FIN; k++) acc += xr[k] * W[k*DD + d];
    g_hA[idx] = acc;
}

__global__ void k_zero_mean() {
    int i = blockIdx.x*blockDim.x + threadIdx.x;     // SEGS*DD/4 threads exactly
    ((float4*)g_mean)[i] = make_float4(0.f, 0.f, 0.f, 0.f);
}

// One warp per edge: mean[dst*R+rel, :] += h[src,:] * inv_cnt[dst*R+rel]
// (linearity: mean-then-transform == transform-then-mean)
__global__ void k_scatter(const float* __restrict__ h,
                          const int* __restrict__ ei, const int* __restrict__ ea) {
    int t = blockIdx.x*blockDim.x + threadIdx.x;     // EE*32 threads exactly
    int e = t >> 5, lane = t & 31;
    int s   = ei[e];
    int seg = ei[EE + e]*RR + ea[e];
    float w = g_inv[seg];
    float4 v = *(const float4*)(h + (size_t)s*DD + lane*4);
    float* p = g_mean + (size_t)seg*DD + lane*4;
    asm volatile("red.global.add.v4.f32 [%0], {%1,%2,%3,%4};"
                 :: "l"(p), "f"(v.x*w), "f"(v.y*w), "f"(v.z*w), "f"(v.w*w)
                 : "memory");
}

// C[65536,128] = relu( A1[65536,128]@B1[128,128] + g_mean[65536,512]@B2[512,128] + bias )
// Tiled SIMT fp32 GEMM: BM=128, BN=128, BK=16, 256 threads, 8x8 micro-tile.
__global__ __launch_bounds__(256, 2) void k_gemm(
    const float* __restrict__ A1,
    const float* __restrict__ B1,    // W_root[l]  [128,128]
    const float* __restrict__ B2,    // W_rel[l]   [512,128] (r*128+d major)
    const float* __restrict__ bias,
    float* __restrict__ C)
{
    __shared__ float As[16][132];    // transposed A tile, padded
    __shared__ float Bs[16][128];
    int tid  = threadIdx.x;
    int row0 = blockIdx.x * 128;
    int ty = tid >> 4, tx = tid & 15;
    float acc[8][8] = {};

    for (int kt = 0; kt < 40; kt++) {
        int k0 = kt * 16;
        const float* Asrc; int lda, kA;
        const float* Bsrc;
        if (k0 < DD) { Asrc = A1;     lda = DD;   kA = k0;      Bsrc = B1 + k0*DD; }
        else         { Asrc = g_mean; lda = KCAT; kA = k0 - DD; Bsrc = B2 + (k0-DD)*DD; }

        __syncthreads();
        #pragma unroll
        for (int i = 0; i < 2; i++) {
            int id  = i*256 + tid;              // 0..511
            int ar  = id >> 2, akk = (id & 3) * 4;
            float4 a = *(const float4*)(Asrc + (size_t)(row0 + ar)*lda + kA + akk);
            As[akk+0][ar] = a.x; As[akk+1][ar] = a.y;
            As[akk+2][ar] = a.z; As[akk+3][ar] = a.w;
            int br = id >> 5, bc = (id & 31) * 4;
            *(float4*)&Bs[br][bc] = *(const float4*)(Bsrc + br*DD + bc);
        }
        __syncthreads();

        #pragma unroll
        for (int k = 0; k < 16; k++) {
            float4 a0 = *(const float4*)&As[k][ty*8];
            float4 a1 = *(const float4*)&As[k][ty*8 + 4];
            float4 b0 = *(const float4*)&Bs[k][tx*8];
            float4 b1 = *(const float4*)&Bs[k][tx*8 + 4];
            float av[8] = {a0.x,a0.y,a0.z,a0.w,a1.x,a1.y,a1.z,a1.w};
            float bv[8] = {b0.x,b0.y,b0.z,b0.w,b1.x,b1.y,b1.z,b1.w};
            #pragma unroll
            for (int ii = 0; ii < 8; ii++)
                #pragma unroll
                for (int jj = 0; jj < 8; jj++)
                    acc[ii][jj] += av[ii]*bv[jj];
        }
    }

    #pragma unroll
    for (int ii = 0; ii < 8; ii++) {
        int r = row0 + ty*8 + ii;
        #pragma unroll
        for (int jj = 0; jj < 8; jj++) {
            int n = tx*8 + jj;
            float v = acc[ii][jj] + bias[n];
            C[(size_t)r*DD + n] = v > 0.f ? v : 0.f;
        }
    }
}

// per-graph max over the 128 nodes
__global__ void k_pool(const float* __restrict__ h, float* __restrict__ out) {
    int g = blockIdx.x, d = threadIdx.x;
    const float* base = h + (size_t)g*128*DD + d;
    float m = base[0];
    #pragma unroll 8
    for (int n = 1; n < 128; n++) m = fmaxf(m, base[(size_t)n*DD]);
    out[g*DD + d] = m;
}

extern "C" void kernel_launch(void* const* d_in, const int* in_sizes, int n_in,
                              void* d_out, int out_size) {
    const float* x      = (const float*)d_in[0];
    const int*   ei     = (const int*)  d_in[1];   // [2,E] (src row 0, dst row 1)
    const int*   ea     = (const int*)  d_in[2];   // [E]
    const float* W_emb  = (const float*)d_in[3];   // [64,128]
    const float* b_emb  = (const float*)d_in[4];   // [128]
    const float* W_root = (const float*)d_in[5];   // [2,128,128]
    const float* W_rel  = (const float*)d_in[6];   // [2,4,128,128]
    const float* bias   = (const float*)d_in[7];   // [2,128]
    float* out = (float*)d_out;

    float *hA, *hB;
    cudaGetSymbolAddress((void**)&hA, g_hA);
    cudaGetSymbolAddress((void**)&hB, g_hB);

    k_zero_cnt<<<SEGS/256, 256>>>();
    k_count<<<EE/256, 256>>>(ei, ea);
    k_inv<<<SEGS/256, 256>>>();
    k_embed<<<(NN*DD)/256, 256>>>(x, W_emb, b_emb);

    const float* hin = hA;
    float* hout = hB;
    for (int l = 0; l < 2; l++) {
        k_zero_mean<<<(SEGS*DD/4)/256, 256>>>();
        k_scatter<<<(EE*32)/256, 256>>>(hin, ei, ea);
        k_gemm<<<NN/128, 256>>>(hin, W_root + (size_t)l*DD*DD,
                                W_rel + (size_t)l*KCAT*DD, bias + (size_t)l*DD, hout);
        float* t = (float*)hin; hin = hout; hout = t;
    }
    k_pool<<<GG, DD>>>(hin, out);
}

// round 3
// speedup vs baseline: 1.5347x; 1.5347x over previous
#include <cuda_runtime.h>

#define NN   65536          // total nodes (G*N)
#define FIN  64
#define DD   128
#define RR   4
#define EE   1572864
#define GG   512
#define SEGS (NN*RR)        // 262144 (node,relation) segments
#define KCAT (RR*DD)        // 512

// ---- scratch (static device globals; no runtime allocation) ----
__device__ __align__(16) float g_hA[(size_t)NN*DD];       // 32 MB
__device__ __align__(16) float g_hB[(size_t)NN*DD];       // 32 MB
__device__ __align__(16) float g_mean[(size_t)SEGS*DD];   // 134 MB
__device__ __align__(16) int   g_cnt[SEGS];
__device__ __align__(16) int   g_off[SEGS];
__device__ int   g_cur[SEGS];
__device__ int   g_bsum[256];
__device__ int   g_csr[EE];

// ---------------- CSR build ----------------
__global__ void k_zero_cnt() {
    int i = blockIdx.x*blockDim.x + threadIdx.x;
    if (i < SEGS) g_cnt[i] = 0;
}

__global__ void k_count(const int* __restrict__ ei, const int* __restrict__ ea) {
    int e = blockIdx.x*blockDim.x + threadIdx.x;
    if (e < EE) atomicAdd(&g_cnt[ei[EE + e]*RR + ea[e]], 1);
}

// level-1 scan: each block scans 1024 counts (4/thread), writes exclusive
// offsets + block total
__global__ void k_scan1() {
    __shared__ int s[256];
    int tid = threadIdx.x;
    int base = blockIdx.x*1024 + tid*4;
    int4 c = *(const int4*)&g_cnt[base];
    int sum = c.x + c.y + c.z + c.w;
    s[tid] = sum;
    __syncthreads();
    #pragma unroll
    for (int off = 1; off < 256; off <<= 1) {
        int v = (tid >= off) ? s[tid - off] : 0;
        __syncthreads();
        s[tid] += v;
        __syncthreads();
    }
    int excl = s[tid] - sum;
    int4 o;
    o.x = excl; o.y = o.x + c.x; o.z = o.y + c.y; o.w = o.z + c.z;
    *(int4*)&g_off[base] = o;
    if (tid == 255) g_bsum[blockIdx.x] = s[255];
}

// level-2: exclusive scan of 256 block sums (single block)
__global__ void k_scan2() {
    __shared__ int s[256];
    int tid = threadIdx.x;
    int v0 = g_bsum[tid];
    s[tid] = v0;
    __syncthreads();
    #pragma unroll
    for (int off = 1; off < 256; off <<= 1) {
        int v = (tid >= off) ? s[tid - off] : 0;
        __syncthreads();
        s[tid] += v;
        __syncthreads();
    }
    g_bsum[tid] = s[tid] - v0;
}

// level-3: add block bases, init cursors
__global__ void k_scan3() {
    int i = blockIdx.x*blockDim.x + threadIdx.x;
    int o = g_off[i] + g_bsum[i >> 10];
    g_off[i] = o;
    g_cur[i] = o;
}

__global__ void k_fill(const int* __restrict__ ei, const int* __restrict__ ea) {
    int e = blockIdx.x*blockDim.x + threadIdx.x;
    if (e >= EE) return;
    int seg = ei[EE + e]*RR + ea[e];
    int pos = atomicAdd(&g_cur[seg], 1);
    g_csr[pos] = ei[e];                       // src node
}

// ---------------- embed: h = x @ W_emb + b_emb (smem-blocked) ----------------
__global__ __launch_bounds__(256) void k_embed(
    const float* __restrict__ x, const float* __restrict__ W,
    const float* __restrict__ b)
{
    __shared__ float xs[64][64];     // 16 KB
    __shared__ float ws[64][128];    // 32 KB
    int tid = threadIdx.x;
    int row0 = blockIdx.x * 64;

    #pragma unroll
    for (int i = 0; i < 4; i++) {                 // x tile: 1024 float4
        int id = i*256 + tid;
        int r = id >> 4, c4 = (id & 15) * 4;
        *(float4*)&xs[r][c4] = *(const float4*)(x + (size_t)(row0 + r)*FIN + c4);
    }
    #pragma unroll
    for (int i = 0; i < 8; i++) {                 // W tile: 2048 float4
        int id = i*256 + tid;
        int r = id >> 5, c4 = (id & 31) * 4;
        *(float4*)&ws[r][c4] = *(const float4*)(W + r*DD + c4);
    }
    __syncthreads();

    int ty = tid >> 5, tx = tid & 31;             // 8 node-rows x 32 col-quads
    float acc[8][4] = {};
    #pragma unroll
    for (int k = 0; k < 64; k++) {
        float4 wv = *(const float4*)&ws[k][tx*4];
        #pragma unroll
        for (int i = 0; i < 8; i++) {
            float xv = xs[ty*8 + i][k];
            acc[i][0] += xv*wv.x; acc[i][1] += xv*wv.y;
            acc[i][2] += xv*wv.z; acc[i][3] += xv*wv.w;
        }
    }
    float4 bv = *(const float4*)(b + tx*4);
    #pragma unroll
    for (int i = 0; i < 8; i++) {
        float4 o;
        o.x = acc[i][0] + bv.x; o.y = acc[i][1] + bv.y;
        o.z = acc[i][2] + bv.z; o.w = acc[i][3] + bv.w;
        *(float4*)(g_hA + (size_t)(row0 + ty*8 + i)*DD + tx*4) = o;
    }
}

// ---------------- gather-mean: one warp per (node,relation) segment ----------
__global__ void k_gather(const float* __restrict__ h) {
    int t = blockIdx.x*blockDim.x + threadIdx.x;
    int seg = t >> 5, lane = t & 31;
    int beg = g_off[seg], n = g_cnt[seg];
    float4 acc = make_float4(0.f, 0.f, 0.f, 0.f);
    int i = 0;
    for (; i + 2 <= n; i += 2) {                  // unroll 2 for MLP
        int s0 = g_csr[beg + i], s1 = g_csr[beg + i + 1];
        float4 v0 = *(const float4*)(h + (size_t)s0*DD + lane*4);
        float4 v1 = *(const float4*)(h + (size_t)s1*DD + lane*4);
        acc.x += v0.x + v1.x; acc.y += v0.y + v1.y;
        acc.z += v0.z + v1.z; acc.w += v0.w + v1.w;
    }
    if (i < n) {
        int s0 = g_csr[beg + i];
        float4 v0 = *(const float4*)(h + (size_t)s0*DD + lane*4);
        acc.x += v0.x; acc.y += v0.y; acc.z += v0.z; acc.w += v0.w;
    }
    float inv = 1.0f / (float)(n > 0 ? n : 1);
    acc.x *= inv; acc.y *= inv; acc.z *= inv; acc.w *= inv;
    *(float4*)(g_mean + (size_t)seg*DD + lane*4) = acc;
}

// C[65536,128] = relu( A1@W_root + g_mean[65536,512]@W_rel + bias )
__global__ __launch_bounds__(256, 2) void k_gemm(
    const float* __restrict__ A1,
    const float* __restrict__ B1,    // W_root[l]  [128,128]
    const float* __restrict__ B2,    // W_rel[l]   [512,128]
    const float* __restrict__ bias,
    float* __restrict__ C)
{
    __shared__ float As[16][132];
    __shared__ float Bs[16][128];
    int tid  = threadIdx.x;
    int row0 = blockIdx.x * 128;
    int ty = tid >> 4, tx = tid & 15;
    float acc[8][8] = {};

    for (int kt = 0; kt < 40; kt++) {
        int k0 = kt * 16;
        const float* Asrc; int lda, kA;
        const float* Bsrc;
        if (k0 < DD) { Asrc = A1;     lda = DD;   kA = k0;      Bsrc = B1 + k0*DD; }
        else         { Asrc = g_mean; lda = KCAT; kA = k0 - DD; Bsrc = B2 + (k0-DD)*DD; }

        __syncthreads();
        #pragma unroll
        for (int i = 0; i < 2; i++) {
            int id  = i*256 + tid;
            int ar  = id >> 2, akk = (id & 3) * 4;
            float4 a = *(const float4*)(Asrc + (size_t)(row0 + ar)*lda + kA + akk);
            As[akk+0][ar] = a.x; As[akk+1][ar] = a.y;
            As[akk+2][ar] = a.z; As[akk+3][ar] = a.w;
            int br = id >> 5, bc = (id & 31) * 4;
            *(float4*)&Bs[br][bc] = *(const float4*)(Bsrc + br*DD + bc);
        }
        __syncthreads();

        #pragma unroll
        for (int k = 0; k < 16; k++) {
            float4 a0 = *(const float4*)&As[k][ty*8];
            float4 a1 = *(const float4*)&As[k][ty*8 + 4];
            float4 b0 = *(const float4*)&Bs[k][tx*8];
            float4 b1 = *(const float4*)&Bs[k][tx*8 + 4];
            float av[8] = {a0.x,a0.y,a0.z,a0.w,a1.x,a1.y,a1.z,a1.w};
            float bv[8] = {b0.x,b0.y,b0.z,b0.w,b1.x,b1.y,b1.z,b1.w};
            #pragma unroll
            for (int ii = 0; ii < 8; ii++)
                #pragma unroll
                for (int jj = 0; jj < 8; jj++)
                    acc[ii][jj] += av[ii]*bv[jj];
        }
    }

    #pragma unroll
    for (int ii = 0; ii < 8; ii++) {
        int r = row0 + ty*8 + ii;
        #pragma unroll
        for (int jj = 0; jj < 8; jj++) {
            int n = tx*8 + jj;
            float v = acc[ii][jj] + bias[n];
            C[(size_t)r*DD + n] = v > 0.f ? v : 0.f;
        }
    }
}

// per-graph max over the 128 nodes
__global__ void k_pool(const float* __restrict__ h, float* __restrict__ out) {
    int g = blockIdx.x, d = threadIdx.x;
    const float* base = h + (size_t)g*128*DD + d;
    float m = base[0];
    #pragma unroll 8
    for (int n = 1; n < 128; n++) m = fmaxf(m, base[(size_t)n*DD]);
    out[g*DD + d] = m;
}

extern "C" void kernel_launch(void* const* d_in, const int* in_sizes, int n_in,
                              void* d_out, int out_size) {
    const float* x      = (const float*)d_in[0];
    const int*   ei     = (const int*)  d_in[1];
    const int*   ea     = (const int*)  d_in[2];
    const float* W_emb  = (const float*)d_in[3];
    const float* b_emb  = (const float*)d_in[4];
    const float* W_root = (const float*)d_in[5];
    const float* W_rel  = (const float*)d_in[6];
    const float* bias   = (const float*)d_in[7];
    float* out = (float*)d_out;

    float *hA, *hB;
    cudaGetSymbolAddress((void**)&hA, g_hA);
    cudaGetSymbolAddress((void**)&hB, g_hB);

    k_zero_cnt<<<SEGS/256, 256>>>();
    k_count<<<EE/256, 256>>>(ei, ea);
    k_scan1<<<256, 256>>>();
    k_scan2<<<1, 256>>>();
    k_scan3<<<SEGS/256, 256>>>();
    k_fill<<<EE/256, 256>>>(ei, ea);
    k_embed<<<NN/64, 256>>>(x, W_emb, b_emb);

    const float* hin = hA;
    float* hout = hB;
    for (int l = 0; l < 2; l++) {
        k_gather<<<(SEGS*32)/256, 256>>>(hin);
        k_gemm<<<NN/128, 256>>>(hin, W_root + (size_t)l*DD*DD,
                                W_rel + (size_t)l*KCAT*DD, bias + (size_t)l*DD, hout);
        float* t = (float*)hin; hin = hout; hout = t;
    }
    k_pool<<<GG, DD>>>(hin, out);
}

// round 5
// speedup vs baseline: 2.4910x; 1.6231x over previous
#include <cuda_runtime.h>
#include <cuda_bf16.h>
#include <cstdint>

#define NN   65536          // total nodes (G*N)
#define FIN  64
#define DD   128
#define RR   4
#define EE   1572864
#define GG   512
#define SEGS (NN*RR)        // 262144 (node,relation) segments
#define KCAT (RR*DD)        // 512
#define KTOT 640            // 128 (root) + 512 (rel)

// ---- scratch (static device globals; no runtime allocation) ----
__device__ __align__(16) float g_hA[(size_t)NN*DD];       // 32 MB
__device__ __align__(16) float g_hB[(size_t)NN*DD];       // 32 MB
__device__ __align__(16) float g_mean[(size_t)SEGS*DD];   // 134 MB
__device__ __align__(16) int   g_cnt[SEGS];
__device__ __align__(16) int   g_off[SEGS];
__device__ int   g_cur[SEGS];
__device__ int   g_bsum[256];
__device__ int   g_csr[EE];
// weights split to bf16 hi/lo, transposed to [layer][n=128][k=640]
__device__ __align__(16) __nv_bfloat16 g_Bhi[2*128*KTOT];
__device__ __align__(16) __nv_bfloat16 g_Blo[2*128*KTOT];

// ---------------- helpers ----------------
__device__ __forceinline__ uint32_t smem_u32(const void* p) {
    uint32_t a;
    asm("{ .reg .u64 t; cvta.to.shared.u64 t, %1; cvt.u32.u64 %0, t; }" : "=r"(a) : "l"(p));
    return a;
}
#define SWZ(o) ((o) ^ (((o) >> 3) & 0x70))

__device__ __forceinline__ void ldm_x4(uint32_t* r, uint32_t addr) {
    asm volatile("ldmatrix.sync.aligned.m8n8.x4.shared.b16 {%0,%1,%2,%3}, [%4];"
        : "=r"(r[0]), "=r"(r[1]), "=r"(r[2]), "=r"(r[3]) : "r"(addr));
}
__device__ __forceinline__ void ldm_x2(uint32_t* r, uint32_t addr) {
    asm volatile("ldmatrix.sync.aligned.m8n8.x2.shared.b16 {%0,%1}, [%2];"
        : "=r"(r[0]), "=r"(r[1]) : "r"(addr));
}
__device__ __forceinline__ void mma16816(float* c, const uint32_t* a, const uint32_t* b) {
    asm volatile("mma.sync.aligned.m16n8k16.row.col.f32.bf16.bf16.f32 "
        "{%0,%1,%2,%3}, {%4,%5,%6,%7}, {%8,%9}, {%0,%1,%2,%3};"
        : "+f"(c[0]), "+f"(c[1]), "+f"(c[2]), "+f"(c[3])
        : "r"(a[0]), "r"(a[1]), "r"(a[2]), "r"(a[3]), "r"(b[0]), "r"(b[1]));
}

// ---------------- CSR build ----------------
__global__ void k_zero_cnt() {
    int i = blockIdx.x*blockDim.x + threadIdx.x;
    if (i < SEGS) g_cnt[i] = 0;
}
__global__ void k_count(const int* __restrict__ ei, const int* __restrict__ ea) {
    int e = blockIdx.x*blockDim.x + threadIdx.x;
    if (e < EE) atomicAdd(&g_cnt[ei[EE + e]*RR + ea[e]], 1);
}
__global__ void k_scan1() {
    __shared__ int s[256];
    int tid = threadIdx.x;
    int base = blockIdx.x*1024 + tid*4;
    int4 c = *(const int4*)&g_cnt[base];
    int sum = c.x + c.y + c.z + c.w;
    s[tid] = sum;
    __syncthreads();
    #pragma unroll
    for (int off = 1; off < 256; off <<= 1) {
        int v = (tid >= off) ? s[tid - off] : 0;
        __syncthreads(); s[tid] += v; __syncthreads();
    }
    int excl = s[tid] - sum;
    int4 o; o.x = excl; o.y = o.x + c.x; o.z = o.y + c.y; o.w = o.z + c.z;
    *(int4*)&g_off[base] = o;
    if (tid == 255) g_bsum[blockIdx.x] = s[255];
}
__global__ void k_scan2() {
    __shared__ int s[256];
    int tid = threadIdx.x;
    int v0 = g_bsum[tid];
    s[tid] = v0;
    __syncthreads();
    #pragma unroll
    for (int off = 1; off < 256; off <<= 1) {
        int v = (tid >= off) ? s[tid - off] : 0;
        __syncthreads(); s[tid] += v; __syncthreads();
    }
    g_bsum[tid] = s[tid] - v0;
}
__global__ void k_scan3() {
    int i = blockIdx.x*blockDim.x + threadIdx.x;
    int o = g_off[i] + g_bsum[i >> 10];
    g_off[i] = o; g_cur[i] = o;
}
__global__ void k_fill(const int* __restrict__ ei, const int* __restrict__ ea) {
    int e = blockIdx.x*blockDim.x + threadIdx.x;
    if (e >= EE) return;
    int seg = ei[EE + e]*RR + ea[e];
    int pos = atomicAdd(&g_cur[seg], 1);
    g_csr[pos] = ei[e];
}

// ---------------- weight split: Wcat[k][n] -> bf16 hi/lo at [l][n][k] -------
__global__ void k_wsplit(const float* __restrict__ W_root, const float* __restrict__ W_rel) {
    int idx = blockIdx.x*blockDim.x + threadIdx.x;     // 2*640*128
    int l = idx / (KTOT*DD);
    int rem = idx - l*(KTOT*DD);
    int k = rem >> 7, n = rem & 127;
    float w = (k < DD) ? W_root[(size_t)l*DD*DD + k*DD + n]
                       : W_rel[(size_t)l*KCAT*DD + (k - DD)*DD + n];
    __nv_bfloat16 hi = __float2bfloat16_rn(w);
    __nv_bfloat16 lo = __float2bfloat16_rn(w - __bfloat162float(hi));
    size_t d = ((size_t)l*DD + n)*KTOT + k;
    g_Bhi[d] = hi; g_Blo[d] = lo;
}

// ---------------- embed: h = x @ W_emb + b_emb (smem-blocked) ----------------
__global__ __launch_bounds__(256) void k_embed(
    const float* __restrict__ x, const float* __restrict__ W,
    const float* __restrict__ b)
{
    __shared__ float xs[64][64];
    __shared__ float ws[64][128];
    int tid = threadIdx.x;
    int row0 = blockIdx.x * 64;
    #pragma unroll
    for (int i = 0; i < 4; i++) {
        int id = i*256 + tid;
        int r = id >> 4, c4 = (id & 15) * 4;
        *(float4*)&xs[r][c4] = *(const float4*)(x + (size_t)(row0 + r)*FIN + c4);
    }
    #pragma unroll
    for (int i = 0; i < 8; i++) {
        int id = i*256 + tid;
        int r = id >> 5, c4 = (id & 31) * 4;
        *(float4*)&ws[r][c4] = *(const float4*)(W + r*DD + c4);
    }
    __syncthreads();
    int ty = tid >> 5, tx = tid & 31;
    float acc[8][4] = {};
    #pragma unroll
    for (int k = 0; k < 64; k++) {
        float4 wv = *(const float4*)&ws[k][tx*4];
        #pragma unroll
        for (int i = 0; i < 8; i++) {
            float xv = xs[ty*8 + i][k];
            acc[i][0] += xv*wv.x; acc[i][1] += xv*wv.y;
            acc[i][2] += xv*wv.z; acc[i][3] += xv*wv.w;
        }
    }
    float4 bv = *(const float4*)(b + tx*4);
    #pragma unroll
    for (int i = 0; i < 8; i++) {
        float4 o;
        o.x = acc[i][0] + bv.x; o.y = acc[i][1] + bv.y;
        o.z = acc[i][2] + bv.z; o.w = acc[i][3] + bv.w;
        *(float4*)(g_hA + (size_t)(row0 + ty*8 + i)*DD + tx*4) = o;
    }
}

// ---------------- gather-mean: one warp per (node,relation) segment ----------
__global__ void k_gather(const float* __restrict__ h) {
    int t = blockIdx.x*blockDim.x + threadIdx.x;
    int seg = t >> 5, lane = t & 31;
    int beg = g_off[seg], n = g_cnt[seg];
    float4 acc = make_float4(0.f, 0.f, 0.f, 0.f);
    int i = 0;
    for (; i + 2 <= n; i += 2) {
        int s0 = g_csr[beg + i], s1 = g_csr[beg + i + 1];
        float4 v0 = *(const float4*)(h + (size_t)s0*DD + lane*4);
        float4 v1 = *(const float4*)(h + (size_t)s1*DD + lane*4);
        acc.x += v0.x + v1.x; acc.y += v0.y + v1.y;
        acc.z += v0.z + v1.z; acc.w += v0.w + v1.w;
    }
    if (i < n) {
        int s0 = g_csr[beg + i];
        float4 v0 = *(const float4*)(h + (size_t)s0*DD + lane*4);
        acc.x += v0.x; acc.y += v0.y; acc.z += v0.z; acc.w += v0.w;
    }
    float inv = 1.0f / (float)(n > 0 ? n : 1);
    acc.x *= inv; acc.y *= inv; acc.z *= inv; acc.w *= inv;
    *(float4*)(g_mean + (size_t)seg*DD + lane*4) = acc;
}

// ---------------- tensor-core GEMM via mma.sync (no 'a' features) -----------
// C[65536,128] = relu([h | g_mean] @ [W_root; W_rel] + bias), bf16x3 HMMA.
// BM=128, BN=128, BK=64, 8 warps in 2(m)x4(n), warp tile 64x32.
// smem: Ahi@0 Alo@16K Bhi@32K Blo@48K (each 128 rows x 64 bf16, SW128 swizzle).
#define GEMM_SMEM 65536

__global__ __launch_bounds__(256, 2) void k_gemm_mma(
    const float* __restrict__ A1,
    const __nv_bfloat16* __restrict__ Bhi,
    const __nv_bfloat16* __restrict__ Blo,
    const float* __restrict__ bias,
    float* __restrict__ C)
{
    extern __shared__ char smem[];
    uint32_t sb = smem_u32(smem);
    const uint32_t sbAhi = sb, sbAlo = sb + 16384, sbBhi = sb + 32768, sbBlo = sb + 49152;
    int tid = threadIdx.x, wid = tid >> 5, lane = tid & 31;
    int wm = wid >> 2, wn = wid & 3;            // 2 x 4 warp grid
    int row0 = blockIdx.x * 128;

    float acc[4][4][4];
    #pragma unroll
    for (int i = 0; i < 4; i++)
        #pragma unroll
        for (int j = 0; j < 4; j++)
            #pragma unroll
            for (int q = 0; q < 4; q++) acc[i][j][q] = 0.f;

    for (int kc = 0; kc < 10; kc++) {
        int k0 = kc * 64;
        const float* Asrc; int lda, kA;
        if (k0 < DD) { Asrc = A1; lda = DD; kA = k0; }
        else         { Asrc = g_mean; lda = KCAT; kA = k0 - DD; }

        __syncthreads();   // previous iteration's consumers done with smem
        // A: 128 rows x 64 fp32 -> bf16 hi/lo, SW128-swizzled 128B rows
        #pragma unroll
        for (int i = 0; i < 8; i++) {
            int id = i*256 + tid;                 // 0..2047
            int r = id >> 4, c4 = (id & 15) * 4;
            float4 v = *(const float4*)(Asrc + (size_t)(row0 + r)*lda + kA + c4);
            __nv_bfloat162 h01 = __floats2bfloat162_rn(v.x, v.y);
            __nv_bfloat162 h23 = __floats2bfloat162_rn(v.z, v.w);
            float lx = v.x - __bfloat162float(__low2bfloat16(h01));
            float ly = v.y - __bfloat162float(__high2bfloat16(h01));
            float lz = v.z - __bfloat162float(__low2bfloat16(h23));
            float lw = v.w - __bfloat162float(__high2bfloat16(h23));
            __nv_bfloat162 l01 = __floats2bfloat162_rn(lx, ly);
            __nv_bfloat162 l23 = __floats2bfloat162_rn(lz, lw);
            uint32_t off = SWZ((uint32_t)(r*128 + c4*2));
            uint2 hp, lp;
            hp.x = *(uint32_t*)&h01; hp.y = *(uint32_t*)&h23;
            lp.x = *(uint32_t*)&l01; lp.y = *(uint32_t*)&l23;
            *(uint2*)(smem + (sbAhi - sb) + off) = hp;
            *(uint2*)(smem + (sbAlo - sb) + off) = lp;
        }
        // B: 128 n-rows x 64 k-cols bf16 from pre-split [n][k] arrays
        #pragma unroll
        for (int i = 0; i < 8; i++) {
            int id = i*256 + tid;
            int n = id >> 4, ck = (id & 15) * 4;
            size_t gsrc = (size_t)n*KTOT + k0 + ck;
            uint32_t off = SWZ((uint32_t)(n*128 + ck*2));
            *(uint2*)(smem + 32768 + off) = *(const uint2*)(Bhi + gsrc);
            *(uint2*)(smem + 49152 + off) = *(const uint2*)(Blo + gsrc);
        }
        __syncthreads();

        #pragma unroll
        for (int ks = 0; ks < 4; ks++) {
            int kb = ks * 16;
            // B fragments for this k16 step (4 n-frags, hi+lo)
            uint32_t bhi[4][2], blo[4][2];
            #pragma unroll
            for (int ni = 0; ni < 4; ni++) {
                int n = wn*32 + ni*8 + (lane & 7);
                uint32_t off = SWZ((uint32_t)(n*128 + (kb + ((lane >> 3) & 1)*8)*2));
                ldm_x2(bhi[ni], sbBhi + off);
                ldm_x2(blo[ni], sbBlo + off);
            }
            #pragma unroll
            for (int mi = 0; mi < 4; mi++) {
                int m = wm*64 + mi*16 + (lane & 15);
                uint32_t off = SWZ((uint32_t)(m*128 + (kb + (lane >> 4)*8)*2));
                uint32_t ahi[4], alo[4];
                ldm_x4(ahi, sbAhi + off);
                ldm_x4(alo, sbAlo + off);
                #pragma unroll
                for (int ni = 0; ni < 4; ni++) {
                    mma16816(acc[mi][ni], ahi, bhi[ni]);
                    mma16816(acc[mi][ni], ahi, blo[ni]);
                    mma16816(acc[mi][ni], alo, bhi[ni]);
                }
            }
        }
    }

    // epilogue: bias + relu + store (each lane: 2 cols x 2 row-halves per frag)
    #pragma unroll
    for (int mi = 0; mi < 4; mi++) {
        int r0 = row0 + wm*64 + mi*16 + (lane >> 2);
        #pragma unroll
        for (int ni = 0; ni < 4; ni++) {
            int col = wn*32 + ni*8 + (lane & 3)*2;
            float b0 = __ldg(&bias[col]), b1 = __ldg(&bias[col + 1]);
            float2 o0, o1;
            o0.x = acc[mi][ni][0] + b0; o0.y = acc[mi][ni][1] + b1;
            o1.x = acc[mi][ni][2] + b0; o1.y = acc[mi][ni][3] + b1;
            o0.x = o0.x > 0.f ? o0.x : 0.f; o0.y = o0.y > 0.f ? o0.y : 0.f;
            o1.x = o1.x > 0.f ? o1.x : 0.f; o1.y = o1.y > 0.f ? o1.y : 0.f;
            *(float2*)(C + (size_t)r0*DD + col)       = o0;
            *(float2*)(C + (size_t)(r0 + 8)*DD + col) = o1;
        }
    }
}

// per-graph max over the 128 nodes
__global__ void k_pool(const float* __restrict__ h, float* __restrict__ out) {
    int g = blockIdx.x, d = threadIdx.x;
    const float* base = h + (size_t)g*128*DD + d;
    float m = base[0];
    #pragma unroll 8
    for (int n = 1; n < 128; n++) m = fmaxf(m, base[(size_t)n*DD]);
    out[g*DD + d] = m;
}

extern "C" void kernel_launch(void* const* d_in, const int* in_sizes, int n_in,
                              void* d_out, int out_size) {
    const float* x      = (const float*)d_in[0];
    const int*   ei     = (const int*)  d_in[1];
    const int*   ea     = (const int*)  d_in[2];
    const float* W_emb  = (const float*)d_in[3];
    const float* b_emb  = (const float*)d_in[4];
    const float* W_root = (const float*)d_in[5];
    const float* W_rel  = (const float*)d_in[6];
    const float* bias   = (const float*)d_in[7];
    float* out = (float*)d_out;

    float *hA, *hB;
    cudaGetSymbolAddress((void**)&hA, g_hA);
    cudaGetSymbolAddress((void**)&hB, g_hB);
    __nv_bfloat16 *bhi, *blo;
    cudaGetSymbolAddress((void**)&bhi, g_Bhi);
    cudaGetSymbolAddress((void**)&blo, g_Blo);

    cudaFuncSetAttribute(k_gemm_mma, cudaFuncAttributeMaxDynamicSharedMemorySize, GEMM_SMEM);

    k_zero_cnt<<<SEGS/256, 256>>>();
    k_count<<<EE/256, 256>>>(ei, ea);
    k_scan1<<<256, 256>>>();
    k_scan2<<<1, 256>>>();
    k_scan3<<<SEGS/256, 256>>>();
    k_fill<<<EE/256, 256>>>(ei, ea);
    k_wsplit<<<(2*KTOT*DD)/256, 256>>>(W_root, W_rel);
    k_embed<<<NN/64, 256>>>(x, W_emb, b_emb);

    const float* hin = hA;
    float* hout = hB;
    for (int l = 0; l < 2; l++) {
        k_gather<<<(SEGS*32)/256, 256>>>(hin);
        k_gemm_mma<<<NN/128, 256, GEMM_SMEM>>>(hin,
                bhi + (size_t)l*DD*KTOT, blo + (size_t)l*DD*KTOT,
                bias + (size_t)l*DD, hout);
        float* t = (float*)hin; hin = hout; hout = t;
    }
    k_pool<<<GG, DD>>>(hin, out);
}